// round 8
// baseline (speedup 1.0000x reference)
#include <cuda_runtime.h>

#define IN 784
#define HIDN 64
#define KTOP 20
#define KCH_E 98              // 784/8 k-chunks (encoder)
#define KCH_D 8               // 64/8  k-chunks (decoder)
#define NPAD 832              // 13*64, padded decoder N
#define EPS_GAP 1e-4f

// Pre-split, pre-arranged weights. Layout: [kc][n][k*2+hl] so one thread's 4
// B-scalars per mma tile are a single float4 = (bh(2tg), bl(2tg), bh(2tg+1), bl(2tg+1)).
__device__ float g_Be[KCH_E * 64 * 16];       // 100352 floats
__device__ float g_Bd[KCH_D * NPAD * 16];     // 106496 floats

// ---- tf32 helpers ----
__device__ __forceinline__ unsigned tf32r(float v) {
    unsigned r; asm("cvt.rna.tf32.f32 %0, %1;" : "=r"(r) : "f"(v)); return r;
}
__device__ __forceinline__ void split(float v, unsigned &hi, unsigned &lo) {
    hi = tf32r(v);
    lo = tf32r(v - __uint_as_float(hi));
}
__device__ __forceinline__ void mma8(float* c, const unsigned* a, unsigned b0, unsigned b1) {
    asm volatile(
        "mma.sync.aligned.m16n8k8.row.col.f32.tf32.tf32.f32 "
        "{%0,%1,%2,%3},{%4,%5,%6,%7},{%8,%9},{%0,%1,%2,%3};"
        : "+f"(c[0]), "+f"(c[1]), "+f"(c[2]), "+f"(c[3])
        : "r"(a[0]), "r"(a[1]), "r"(a[2]), "r"(a[3]), "r"(b0), "r"(b1));
}
// 3-term tf32 product-sum; bv = (bh0, bl0, bh1, bl1)
__device__ __forceinline__ void mma3(float* c, const unsigned* ah, const unsigned* al, float4 bv) {
    unsigned bh0 = __float_as_uint(bv.x), bl0 = __float_as_uint(bv.y);
    unsigned bh1 = __float_as_uint(bv.z), bl1 = __float_as_uint(bv.w);
    mma8(c, ah, bh0, bh1);
    mma8(c, al, bh0, bh1);
    mma8(c, ah, bl0, bl1);
}

// ---------------- K0: split + rearrange weights ----------------
__global__ void k_prep(const float* __restrict__ We, const float* __restrict__ Wd) {
    int idx = blockIdx.x * 256 + threadIdx.x;
    const int NE = KCH_E * 1024;
    if (idx < NE) {
        int kc = idx >> 10, r = idx & 1023;
        int n = r >> 4, q = r & 15, kk = q >> 1, hl = q & 1;
        float w = We[n * IN + kc * 8 + kk];
        unsigned h = tf32r(w);
        g_Be[idx] = hl ? __uint_as_float(tf32r(w - __uint_as_float(h)))
                       : __uint_as_float(h);
    }
    int j = idx - NE;
    const int ND = KCH_D * NPAD * 16;
    if (j >= 0 && j < ND) {
        int kc = j / (NPAD * 16);
        int r  = j % (NPAD * 16);
        int n = r >> 4, q = r & 15, kk = q >> 1, hl = q & 1;
        float w = (n < IN) ? Wd[n * HIDN + kc * 8 + kk] : 0.f;
        unsigned h = tf32r(w);
        g_Bd[j] = hl ? __uint_as_float(tf32r(w - __uint_as_float(h)))
                     : __uint_as_float(h);
    }
}

// ---------------- K1: encoder GEMM (3xTF32) + bias + ReLU ----------------
// CTA = 128 rows x 64 cols, 256 thr = 8 warps; warp = 16 rows (one A frag).
// acc[8][4] = 32 regs. B double-buffered; one LDS.128 per (tile,thread).
__global__ __launch_bounds__(256) void k_enc(const float* __restrict__ x,
        const float* __restrict__ benc, float* __restrict__ hout, int B) {
    __shared__ float ws[2][64][16];
    const int tid = threadIdx.x, lane = tid & 31, w = tid >> 5;
    const int g = lane >> 2, tg = lane & 3;
    const int r0 = blockIdx.x * 128;
    const int rowA = r0 + w * 16 + g;                 // rows g, g+8 of warp tile
    const int rA = min(rowA, B - 1), rB = min(rowA + 8, B - 1);
    const float* xa = x + (size_t)rA * IN + 2 * tg;
    const float* xb = x + (size_t)rB * IN + 2 * tg;

    float acc[8][4];
    #pragma unroll
    for (int t = 0; t < 8; t++)
        #pragma unroll
        for (int i = 0; i < 4; i++) acc[t][i] = 0.f;

    ((float4*)ws[0])[tid] = ((const float4*)g_Be)[tid];
    __syncthreads();

    for (int kc = 0; kc < KCH_E; kc++) {
        const int cur = kc & 1;
        const bool more = (kc + 1) < KCH_E;
        float4 pv;
        if (more) pv = ((const float4*)(g_Be + (kc + 1) * 1024))[tid];

        float2 a01 = *(const float2*)(xa + kc * 8);   // (row g, k=2tg / 2tg+1)
        float2 a23 = *(const float2*)(xb + kc * 8);   // (row g+8, ...)
        unsigned ah[4], al[4];
        split(a01.x, ah[0], al[0]);   // frag (g,    k'=tg)   <-> global 2tg
        split(a23.x, ah[1], al[1]);   // frag (g+8,  k'=tg)
        split(a01.y, ah[2], al[2]);   // frag (g,    k'=tg+4) <-> global 2tg+1
        split(a23.y, ah[3], al[3]);   // frag (g+8,  k'=tg+4)

        #pragma unroll
        for (int t = 0; t < 8; t++) {
            float4 bv = *(const float4*)&ws[cur][t * 8 + g][4 * tg];
            mma3(acc[t], ah, al, bv);
        }

        if (more) ((float4*)ws[cur ^ 1])[tid] = pv;
        __syncthreads();
    }

    #pragma unroll
    for (int t = 0; t < 8; t++) {
        int col = t * 8 + 2 * tg;
        float2 bb = *(const float2*)(benc + col);
        if (rowA < B) {
            float2 o = make_float2(fmaxf(acc[t][0] + bb.x, 0.f),
                                   fmaxf(acc[t][1] + bb.y, 0.f));
            *(float2*)(hout + (size_t)rowA * HIDN + col) = o;
        }
        if (rowA + 8 < B) {
            float2 o = make_float2(fmaxf(acc[t][2] + bb.x, 0.f),
                                   fmaxf(acc[t][3] + bb.y, 0.f));
            *(float2*)(hout + (size_t)(rowA + 8) * HIDN + col) = o;
        }
    }
}

// ---------------- K2: top-20 gating + INLINE exact repair of fragile rows ----
// Warp per row. If the 20th/21st gap < EPS_GAP, the tf32 selection/values may
// differ from fp32 -> same warp recomputes the row exactly and regates.
__global__ __launch_bounds__(256) void k_topk(const float* __restrict__ x,
        const float* __restrict__ We, const float* __restrict__ benc,
        float* __restrict__ h, int B) {
    int warp = threadIdx.x >> 5, lane = threadIdx.x & 31;
    int row = blockIdx.x * 8 + warp;
    if (row >= B) return;
    float* hr = h + (size_t)row * HIDN;
    float v0 = hr[lane], v1 = hr[lane + 32];

    unsigned long long k0 = ((unsigned long long)__float_as_uint(v0) << 32) | (unsigned)(63 - lane);
    unsigned long long k1 = ((unsigned long long)__float_as_uint(v1) << 32) | (unsigned)(31 - lane);
    float thr = 0.f, nxt = 0.f;
    #pragma unroll
    for (int it = 0; it < KTOP + 1; it++) {
        unsigned long long m = (k0 > k1) ? k0 : k1;
        #pragma unroll
        for (int off = 16; off > 0; off >>= 1) {
            unsigned long long o = __shfl_xor_sync(0xffffffffu, m, off);
            if (o > m) m = o;
        }
        if (it == KTOP - 1) thr = __uint_as_float((unsigned)(m >> 32));
        if (it == KTOP)     nxt = __uint_as_float((unsigned)(m >> 32));
        if (k0 == m) k0 = 0ull; else if (k1 == m) k1 = 0ull;
    }

    if (thr - nxt >= EPS_GAP) {
        hr[lane]      = (v0 >= thr) ? v0 : 0.f;
        hr[lane + 32] = (v1 >= thr) ? v1 : 0.f;
        return;
    }

    // Fragile: exact fp32 recompute of this row's 64 pre-activations.
    const float* xr = x + (size_t)row * IN;
    const float* wa = We + (size_t)lane * IN;
    const float* wb = We + (size_t)(lane + 32) * IN;
    float a0 = 0.f, a1 = 0.f;
    for (int k = 0; k < IN; k += 4) {
        float4 xv = *(const float4*)(xr + k);
        float4 va = *(const float4*)(wa + k);
        float4 vb = *(const float4*)(wb + k);
        a0 += xv.x*va.x + xv.y*va.y + xv.z*va.z + xv.w*va.w;
        a1 += xv.x*vb.x + xv.y*vb.y + xv.z*vb.z + xv.w*vb.w;
    }
    v0 = fmaxf(a0 + benc[lane], 0.f);
    v1 = fmaxf(a1 + benc[lane + 32], 0.f);
    k0 = ((unsigned long long)__float_as_uint(v0) << 32) | (unsigned)(63 - lane);
    k1 = ((unsigned long long)__float_as_uint(v1) << 32) | (unsigned)(31 - lane);
    thr = 0.f;
    #pragma unroll
    for (int it = 0; it < KTOP; it++) {
        unsigned long long m = (k0 > k1) ? k0 : k1;
        #pragma unroll
        for (int off = 16; off > 0; off >>= 1) {
            unsigned long long o = __shfl_xor_sync(0xffffffffu, m, off);
            if (o > m) m = o;
        }
        if (it == KTOP - 1) thr = __uint_as_float((unsigned)(m >> 32));
        if (k0 == m) k0 = 0ull; else if (k1 == m) k1 = 0ull;
    }
    hr[lane]      = (v0 >= thr) ? v0 : 0.f;
    hr[lane + 32] = (v1 >= thr) ? v1 : 0.f;
}

// ---------------- K3: decoder GEMM (3xTF32) + bias ----------------
// CTA = 128 rows x 64 cols (grid.y = 13), K=64 all staged once in smem.
__global__ __launch_bounds__(256) void k_dec(const float* __restrict__ h,
        const float* __restrict__ bdec, float* __restrict__ xhat, int B) {
    __shared__ float ws[KCH_D][64][16];   // 32 KB
    const int tid = threadIdx.x, lane = tid & 31, w = tid >> 5;
    const int g = lane >> 2, tg = lane & 3;
    const int r0 = blockIdx.x * 128;
    const int n0 = blockIdx.y * 64;
    const int rowA = r0 + w * 16 + g;
    const int rA = min(rowA, B - 1), rB = min(rowA + 8, B - 1);
    const float* ha = h + (size_t)rA * HIDN + 2 * tg;
    const float* hb = h + (size_t)rB * HIDN + 2 * tg;

    // stage all B: 8 kc * 64 n * 16 = 2048 float4 / 256 thr = 8 each
    #pragma unroll
    for (int i = 0; i < 8; i++) {
        int f = tid + i * 256;
        int kc = f >> 8, q = f & 255, n = q >> 2, part = q & 3;
        float4 v = *(const float4*)(g_Bd + ((size_t)kc * NPAD + n0 + n) * 16 + part * 4);
        *(float4*)&ws[kc][n][part * 4] = v;
    }
    __syncthreads();

    float acc[8][4];
    #pragma unroll
    for (int t = 0; t < 8; t++)
        #pragma unroll
        for (int i = 0; i < 4; i++) acc[t][i] = 0.f;

    #pragma unroll
    for (int kc = 0; kc < KCH_D; kc++) {
        float2 a01 = *(const float2*)(ha + kc * 8);
        float2 a23 = *(const float2*)(hb + kc * 8);
        unsigned ah[4], al[4];
        split(a01.x, ah[0], al[0]);
        split(a23.x, ah[1], al[1]);
        split(a01.y, ah[2], al[2]);
        split(a23.y, ah[3], al[3]);
        #pragma unroll
        for (int t = 0; t < 8; t++) {
            float4 bv = *(const float4*)&ws[kc][t * 8 + g][4 * tg];
            mma3(acc[t], ah, al, bv);
        }
    }

    #pragma unroll
    for (int t = 0; t < 8; t++) {
        int col = n0 + t * 8 + 2 * tg;
        if (col < IN) {
            float2 bb = *(const float2*)(bdec + col);
            if (rowA < B) {
                float2 o = make_float2(acc[t][0] + bb.x, acc[t][1] + bb.y);
                *(float2*)(xhat + (size_t)rowA * IN + col) = o;
            }
            if (rowA + 8 < B) {
                float2 o = make_float2(acc[t][2] + bb.x, acc[t][3] + bb.y);
                *(float2*)(xhat + (size_t)(rowA + 8) * IN + col) = o;
            }
        }
    }
}

extern "C" void kernel_launch(void* const* d_in, const int* in_sizes, int n_in,
                              void* d_out, int out_size) {
    const float* x    = (const float*)d_in[0];
    const float* We   = (const float*)d_in[1];
    const float* benc = (const float*)d_in[2];
    const float* Wd   = (const float*)d_in[3];
    const float* bdec = (const float*)d_in[4];
    int B = in_sizes[0] / IN;

    float* hout = (float*)d_out;                         // [B, 64]
    float* xhat = (float*)d_out + (size_t)B * HIDN;      // [B, 784]

    const int NPREP = KCH_E * 1024 + KCH_D * NPAD * 16;
    k_prep<<<(NPREP + 255) / 256, 256>>>(We, Wd);
    k_enc<<<(B + 127) / 128, 256>>>(x, benc, hout, B);
    k_topk<<<(B + 7) / 8, 256>>>(x, We, benc, hout, B);
    k_dec<<<dim3((B + 127) / 128, 13), 256>>>(hout, bdec, xhat, B);
}

// round 9
// speedup vs baseline: 1.0636x; 1.0636x over previous
#include <cuda_runtime.h>

#define IN 784
#define HIDN 64
#define KTOP 20
#define KCH_E 98              // 784/8 k-chunks (encoder)
#define KCH_D 8               // 64/8  k-chunks (decoder)
#define NPAD 832              // 13*64, padded decoder N
#define EPS_GAP 1e-4f

// Pre-split weights. Layout [kc][n][k*2+hl]: one thread's 4 B-scalars per mma
// tile = one float4 = (bh(2tg), bl(2tg), bh(2tg+1), bl(2tg+1)).
__device__ float g_Be[KCH_E * 64 * 16];       // 100352 floats
__device__ float g_Bd[KCH_D * NPAD * 16];     // 106496 floats

// ---- tf32 helpers ----
__device__ __forceinline__ unsigned tf32r(float v) {
    unsigned r; asm("cvt.rna.tf32.f32 %0, %1;" : "=r"(r) : "f"(v)); return r;
}
__device__ __forceinline__ void split(float v, unsigned &hi, unsigned &lo) {
    hi = tf32r(v);
    lo = tf32r(v - __uint_as_float(hi));
}
__device__ __forceinline__ void mma8(float* c, const unsigned* a, unsigned b0, unsigned b1) {
    asm volatile(
        "mma.sync.aligned.m16n8k8.row.col.f32.tf32.tf32.f32 "
        "{%0,%1,%2,%3},{%4,%5,%6,%7},{%8,%9},{%0,%1,%2,%3};"
        : "+f"(c[0]), "+f"(c[1]), "+f"(c[2]), "+f"(c[3])
        : "r"(a[0]), "r"(a[1]), "r"(a[2]), "r"(a[3]), "r"(b0), "r"(b1));
}
__device__ __forceinline__ void mma3(float* c, const unsigned* ah, const unsigned* al, float4 bv) {
    unsigned bh0 = __float_as_uint(bv.x), bl0 = __float_as_uint(bv.y);
    unsigned bh1 = __float_as_uint(bv.z), bl1 = __float_as_uint(bv.w);
    mma8(c, ah, bh0, bh1);
    mma8(c, al, bh0, bh1);
    mma8(c, ah, bl0, bl1);
}
// ---- cp.async ----
__device__ __forceinline__ void cp16(void* sdst, const void* gsrc) {
    unsigned sa = (unsigned)__cvta_generic_to_shared(sdst);
    asm volatile("cp.async.ca.shared.global [%0], [%1], 16;" :: "r"(sa), "l"(gsrc));
}
#define CP_COMMIT() asm volatile("cp.async.commit_group;")
#define CP_WAIT2()  asm volatile("cp.async.wait_group 2;" ::: "memory")

// ---------------- K0: split + rearrange weights ----------------
__global__ void k_prep(const float* __restrict__ We, const float* __restrict__ Wd) {
    int idx = blockIdx.x * 256 + threadIdx.x;
    const int NE = KCH_E * 1024;
    if (idx < NE) {
        int kc = idx >> 10, r = idx & 1023;
        int n = r >> 4, q = r & 15, kk = q >> 1, hl = q & 1;
        float w = We[n * IN + kc * 8 + kk];
        unsigned h = tf32r(w);
        g_Be[idx] = hl ? __uint_as_float(tf32r(w - __uint_as_float(h)))
                       : __uint_as_float(h);
    }
    int j = idx - NE;
    const int ND = KCH_D * NPAD * 16;
    if (j >= 0 && j < ND) {
        int kc = j / (NPAD * 16);
        int r  = j % (NPAD * 16);
        int n = r >> 4, q = r & 15, kk = q >> 1, hl = q & 1;
        float w = (n < IN) ? Wd[n * HIDN + kc * 8 + kk] : 0.f;
        unsigned h = tf32r(w);
        g_Bd[j] = hl ? __uint_as_float(tf32r(w - __uint_as_float(h)))
                     : __uint_as_float(h);
    }
}

// ---------------- K1: encoder GEMM (3xTF32) + bias + ReLU ----------------
// CTA = 256 rows x 64 cols, 8 warps, warp = 32 rows (two A frags).
// 4-stage cp.async pipeline for both x (8KB/stage) and B (4KB/stage).
__global__ __launch_bounds__(256, 2) void k_enc(const float* __restrict__ x,
        const float* __restrict__ benc, float* __restrict__ hout, int B) {
    __shared__ float xs[4][256][8];    // [stage][row][k]  32 KB
    __shared__ float ws[4][64][16];    // [stage][n][k*2+hl] 16 KB
    const int tid = threadIdx.x, lane = tid & 31, w = tid >> 5;
    const int g = lane >> 2, tg = lane & 3;
    const int r0 = blockIdx.x * 256;
    const long xrow = (long)min(r0 + tid, B - 1) * IN;   // one x-row per thread

    float acc[8][8];
    #pragma unroll
    for (int t = 0; t < 8; t++)
        #pragma unroll
        for (int i = 0; i < 8; i++) acc[t][i] = 0.f;

    // prologue: stages 0..2 in flight
    #pragma unroll
    for (int s = 0; s < 3; s++) {
        cp16(&ws[s][0][0] + tid * 4, g_Be + s * 1024 + tid * 4);
        cp16(&xs[s][tid][0], x + xrow + s * 8);
        cp16(&xs[s][tid][4], x + xrow + s * 8 + 4);
        CP_COMMIT();
    }

    const int mr = w * 32;
    for (int kc = 0; kc < KCH_E; kc++) {
        const int cur = kc & 3;
        CP_WAIT2();
        __syncthreads();

        // issue stage kc+3 (overwrites stage read at kc-1; barrier above orders it)
        if (kc + 3 < KCH_E) {
            const int s = (kc + 3) & 3;
            cp16(&ws[s][0][0] + tid * 4, g_Be + (kc + 3) * 1024 + tid * 4);
            cp16(&xs[s][tid][0], x + xrow + (kc + 3) * 8);
            cp16(&xs[s][tid][4], x + xrow + (kc + 3) * 8 + 4);
            CP_COMMIT();
        }

        float2 a0 = *(const float2*)&xs[cur][mr + g     ][2 * tg];
        float2 a1 = *(const float2*)&xs[cur][mr + g +  8][2 * tg];
        float2 a2 = *(const float2*)&xs[cur][mr + g + 16][2 * tg];
        float2 a3 = *(const float2*)&xs[cur][mr + g + 24][2 * tg];
        unsigned ah0[4], al0[4], ah1[4], al1[4];
        split(a0.x, ah0[0], al0[0]); split(a1.x, ah0[1], al0[1]);
        split(a0.y, ah0[2], al0[2]); split(a1.y, ah0[3], al0[3]);
        split(a2.x, ah1[0], al1[0]); split(a3.x, ah1[1], al1[1]);
        split(a2.y, ah1[2], al1[2]); split(a3.y, ah1[3], al1[3]);

        #pragma unroll
        for (int t = 0; t < 8; t++) {
            float4 bv = *(const float4*)&ws[cur][t * 8 + g][4 * tg];
            mma3(acc[t],     ah0, al0, bv);
            mma3(acc[t] + 4, ah1, al1, bv);
        }
        // single barrier per chunk (top of next iteration)
    }

    const int rowb = r0 + mr + g;
    #pragma unroll
    for (int t = 0; t < 8; t++) {
        int col = t * 8 + 2 * tg;
        float2 bb = *(const float2*)(benc + col);
        #pragma unroll
        for (int s = 0; s < 4; s++) {
            int r = rowb + 8 * s;
            if (r < B) {
                float u0 = (s & 1) ? acc[t][(s >> 1) * 4 + 2] : acc[t][(s >> 1) * 4 + 0];
                float u1 = (s & 1) ? acc[t][(s >> 1) * 4 + 3] : acc[t][(s >> 1) * 4 + 1];
                float2 o = make_float2(fmaxf(u0 + bb.x, 0.f), fmaxf(u1 + bb.y, 0.f));
                *(float2*)(hout + (size_t)r * HIDN + col) = o;
            }
        }
    }
}

// ---------------- K2: top-20 gating + inline exact repair of fragile rows ----
__global__ __launch_bounds__(256) void k_topk(const float* __restrict__ x,
        const float* __restrict__ We, const float* __restrict__ benc,
        float* __restrict__ h, int B) {
    int warp = threadIdx.x >> 5, lane = threadIdx.x & 31;
    int row = blockIdx.x * 8 + warp;
    if (row >= B) return;
    float* hr = h + (size_t)row * HIDN;
    float v0 = hr[lane], v1 = hr[lane + 32];

    unsigned long long k0 = ((unsigned long long)__float_as_uint(v0) << 32) | (unsigned)(63 - lane);
    unsigned long long k1 = ((unsigned long long)__float_as_uint(v1) << 32) | (unsigned)(31 - lane);
    float thr = 0.f, nxt = 0.f;
    #pragma unroll
    for (int it = 0; it < KTOP + 1; it++) {
        unsigned long long m = (k0 > k1) ? k0 : k1;
        #pragma unroll
        for (int off = 16; off > 0; off >>= 1) {
            unsigned long long o = __shfl_xor_sync(0xffffffffu, m, off);
            if (o > m) m = o;
        }
        if (it == KTOP - 1) thr = __uint_as_float((unsigned)(m >> 32));
        if (it == KTOP)     nxt = __uint_as_float((unsigned)(m >> 32));
        if (k0 == m) k0 = 0ull; else if (k1 == m) k1 = 0ull;
    }

    if (thr - nxt >= EPS_GAP) {
        hr[lane]      = (v0 >= thr) ? v0 : 0.f;
        hr[lane + 32] = (v1 >= thr) ? v1 : 0.f;
        return;
    }

    // Fragile: exact fp32 recompute of this row.
    const float* xr = x + (size_t)row * IN;
    const float* wa = We + (size_t)lane * IN;
    const float* wb = We + (size_t)(lane + 32) * IN;
    float a0 = 0.f, a1 = 0.f;
    for (int k = 0; k < IN; k += 4) {
        float4 xv = *(const float4*)(xr + k);
        float4 va = *(const float4*)(wa + k);
        float4 vb = *(const float4*)(wb + k);
        a0 += xv.x*va.x + xv.y*va.y + xv.z*va.z + xv.w*va.w;
        a1 += xv.x*vb.x + xv.y*vb.y + xv.z*vb.z + xv.w*vb.w;
    }
    v0 = fmaxf(a0 + benc[lane], 0.f);
    v1 = fmaxf(a1 + benc[lane + 32], 0.f);
    k0 = ((unsigned long long)__float_as_uint(v0) << 32) | (unsigned)(63 - lane);
    k1 = ((unsigned long long)__float_as_uint(v1) << 32) | (unsigned)(31 - lane);
    thr = 0.f;
    #pragma unroll
    for (int it = 0; it < KTOP; it++) {
        unsigned long long m = (k0 > k1) ? k0 : k1;
        #pragma unroll
        for (int off = 16; off > 0; off >>= 1) {
            unsigned long long o = __shfl_xor_sync(0xffffffffu, m, off);
            if (o > m) m = o;
        }
        if (it == KTOP - 1) thr = __uint_as_float((unsigned)(m >> 32));
        if (k0 == m) k0 = 0ull; else if (k1 == m) k1 = 0ull;
    }
    hr[lane]      = (v0 >= thr) ? v0 : 0.f;
    hr[lane + 32] = (v1 >= thr) ? v1 : 0.f;
}

// ---------------- K3: decoder GEMM (3xTF32) + bias ----------------
// CTA = 256 rows x 64 cols (grid.y = 13), warp = 32 rows, K=64 staged once.
__global__ __launch_bounds__(256, 2) void k_dec(const float* __restrict__ h,
        const float* __restrict__ bdec, float* __restrict__ xhat, int B) {
    __shared__ float ws[KCH_D][64][16];   // 32 KB
    const int tid = threadIdx.x, lane = tid & 31, w = tid >> 5;
    const int g = lane >> 2, tg = lane & 3;
    const int r0 = blockIdx.x * 256;
    const int n0 = blockIdx.y * 64;
    const int rowb = r0 + w * 32 + g;
    const float* hp[4];
    #pragma unroll
    for (int j = 0; j < 4; j++) {
        int r = min(rowb + 8 * j, B - 1);
        hp[j] = h + (size_t)r * HIDN + 2 * tg;
    }

    // stage all B via cp.async: 2048 float4 / 256 thr = 8 each
    #pragma unroll
    for (int i = 0; i < 8; i++) {
        int f = tid + i * 256;
        int kc = f >> 8, q = f & 255, n = q >> 2, part = q & 3;
        cp16(&ws[kc][n][part * 4],
             g_Bd + ((size_t)kc * NPAD + n0 + n) * 16 + part * 4);
    }
    CP_COMMIT();
    asm volatile("cp.async.wait_group 0;" ::: "memory");
    __syncthreads();

    float acc[8][8];
    #pragma unroll
    for (int t = 0; t < 8; t++)
        #pragma unroll
        for (int i = 0; i < 8; i++) acc[t][i] = 0.f;

    #pragma unroll
    for (int kc = 0; kc < KCH_D; kc++) {
        float2 a0 = *(const float2*)(hp[0] + kc * 8);
        float2 a1 = *(const float2*)(hp[1] + kc * 8);
        float2 a2 = *(const float2*)(hp[2] + kc * 8);
        float2 a3 = *(const float2*)(hp[3] + kc * 8);
        unsigned ah0[4], al0[4], ah1[4], al1[4];
        split(a0.x, ah0[0], al0[0]); split(a1.x, ah0[1], al0[1]);
        split(a0.y, ah0[2], al0[2]); split(a1.y, ah0[3], al0[3]);
        split(a2.x, ah1[0], al1[0]); split(a3.x, ah1[1], al1[1]);
        split(a2.y, ah1[2], al1[2]); split(a3.y, ah1[3], al1[3]);
        #pragma unroll
        for (int t = 0; t < 8; t++) {
            float4 bv = *(const float4*)&ws[kc][t * 8 + g][4 * tg];
            mma3(acc[t],     ah0, al0, bv);
            mma3(acc[t] + 4, ah1, al1, bv);
        }
    }

    #pragma unroll
    for (int t = 0; t < 8; t++) {
        int col = n0 + t * 8 + 2 * tg;
        if (col < IN) {
            float2 bb = *(const float2*)(bdec + col);
            #pragma unroll
            for (int s = 0; s < 4; s++) {
                int r = rowb + 8 * s;
                if (r < B) {
                    float u0 = (s & 1) ? acc[t][(s >> 1) * 4 + 2] : acc[t][(s >> 1) * 4 + 0];
                    float u1 = (s & 1) ? acc[t][(s >> 1) * 4 + 3] : acc[t][(s >> 1) * 4 + 1];
                    float2 o = make_float2(u0 + bb.x, u1 + bb.y);
                    *(float2*)(xhat + (size_t)r * IN + col) = o;
                }
            }
        }
    }
}

extern "C" void kernel_launch(void* const* d_in, const int* in_sizes, int n_in,
                              void* d_out, int out_size) {
    const float* x    = (const float*)d_in[0];
    const float* We   = (const float*)d_in[1];
    const float* benc = (const float*)d_in[2];
    const float* Wd   = (const float*)d_in[3];
    const float* bdec = (const float*)d_in[4];
    int B = in_sizes[0] / IN;

    float* hout = (float*)d_out;                         // [B, 64]
    float* xhat = (float*)d_out + (size_t)B * HIDN;      // [B, 784]

    const int NPREP = KCH_E * 1024 + KCH_D * NPAD * 16;
    k_prep<<<(NPREP + 255) / 256, 256>>>(We, Wd);
    k_enc<<<(B + 255) / 256, 256>>>(x, benc, hout, B);
    k_topk<<<(B + 7) / 8, 256>>>(x, We, benc, hout, B);
    k_dec<<<dim3((B + 255) / 256, 13), 256>>>(hout, bdec, xhat, B);
}

// round 10
// speedup vs baseline: 1.1319x; 1.0642x over previous
#include <cuda_runtime.h>

#define IN 784
#define HIDN 64
#define KTOP 20
#define KCH_E 98              // 784/8 k-chunks (encoder)
#define KCH_D 8               // 64/8  k-chunks (decoder)
#define NPAD 832              // 13*64, padded decoder N
#define EPS_GAP 1e-4f

// Pre-split weights. Layout [kc][n][k*2+hl]: one thread's 4 B-scalars per mma
// tile = one float4 = (bh(2tg), bl(2tg), bh(2tg+1), bl(2tg+1)).
__device__ float g_Be[KCH_E * 64 * 16];       // 100352 floats
__device__ float g_Bd[KCH_D * NPAD * 16];     // 106496 floats

// ---- tf32 helpers ----
__device__ __forceinline__ unsigned tf32r(float v) {
    unsigned r; asm("cvt.rna.tf32.f32 %0, %1;" : "=r"(r) : "f"(v)); return r;
}
// Fast split: tf32 HMMA reads only bits[31:13] of the register, so hi can be a
// mask (LOP3) and lo can be the raw residual (HW truncation adds ~2^-20 rel
// error, far under the EPS_GAP repair margin). No slow cvt in hot loops.
__device__ __forceinline__ void splitm(float v, unsigned &hi, unsigned &lo) {
    unsigned b = __float_as_uint(v);
    hi = b & 0xFFFFE000u;
    lo = __float_as_uint(v - __uint_as_float(hi));
}
__device__ __forceinline__ void mma8(float* c, const unsigned* a, unsigned b0, unsigned b1) {
    asm volatile(
        "mma.sync.aligned.m16n8k8.row.col.f32.tf32.tf32.f32 "
        "{%0,%1,%2,%3},{%4,%5,%6,%7},{%8,%9},{%0,%1,%2,%3};"
        : "+f"(c[0]), "+f"(c[1]), "+f"(c[2]), "+f"(c[3])
        : "r"(a[0]), "r"(a[1]), "r"(a[2]), "r"(a[3]), "r"(b0), "r"(b1));
}
__device__ __forceinline__ void mma3(float* c, const unsigned* ah, const unsigned* al, float4 bv) {
    unsigned bh0 = __float_as_uint(bv.x), bl0 = __float_as_uint(bv.y);
    unsigned bh1 = __float_as_uint(bv.z), bl1 = __float_as_uint(bv.w);
    mma8(c, ah, bh0, bh1);
    mma8(c, al, bh0, bh1);
    mma8(c, ah, bl0, bl1);
}
// ---- cp.async ----
__device__ __forceinline__ void cp16(void* sdst, const void* gsrc) {
    unsigned sa = (unsigned)__cvta_generic_to_shared(sdst);
    asm volatile("cp.async.ca.shared.global [%0], [%1], 16;" :: "r"(sa), "l"(gsrc));
}
#define CP_COMMIT() asm volatile("cp.async.commit_group;")
#define CP_WAIT2()  asm volatile("cp.async.wait_group 2;" ::: "memory")

// ---------------- K0: split + rearrange weights (rounded split, one-time) ----
__global__ void k_prep(const float* __restrict__ We, const float* __restrict__ Wd) {
    int idx = blockIdx.x * 256 + threadIdx.x;
    const int NE = KCH_E * 1024;
    if (idx < NE) {
        int kc = idx >> 10, r = idx & 1023;
        int n = r >> 4, q = r & 15, kk = q >> 1, hl = q & 1;
        float w = We[n * IN + kc * 8 + kk];
        unsigned h = tf32r(w);
        g_Be[idx] = hl ? __uint_as_float(tf32r(w - __uint_as_float(h)))
                       : __uint_as_float(h);
    }
    int j = idx - NE;
    const int ND = KCH_D * NPAD * 16;
    if (j >= 0 && j < ND) {
        int kc = j / (NPAD * 16);
        int r  = j % (NPAD * 16);
        int n = r >> 4, q = r & 15, kk = q >> 1, hl = q & 1;
        float w = (n < IN) ? Wd[n * HIDN + kc * 8 + kk] : 0.f;
        unsigned h = tf32r(w);
        g_Bd[j] = hl ? __uint_as_float(tf32r(w - __uint_as_float(h)))
                     : __uint_as_float(h);
    }
}

// ---------------- K1: encoder GEMM (3xTF32) + bias + ReLU ----------------
// CTA = 256 rows x 64 cols, 8 warps, warp = 32 rows (two A frags).
// 4-stage cp.async pipeline for x (8KB/stage) and B (4KB/stage).
__global__ __launch_bounds__(256, 2) void k_enc(const float* __restrict__ x,
        const float* __restrict__ benc, float* __restrict__ hout, int B) {
    __shared__ float xs[4][256][8];    // [stage][row][k]  32 KB
    __shared__ float ws[4][64][16];    // [stage][n][k*2+hl] 16 KB
    const int tid = threadIdx.x, lane = tid & 31, w = tid >> 5;
    const int g = lane >> 2, tg = lane & 3;
    const int r0 = blockIdx.x * 256;
    const long xrow = (long)min(r0 + tid, B - 1) * IN;   // one x-row per thread

    float acc[8][8];
    #pragma unroll
    for (int t = 0; t < 8; t++)
        #pragma unroll
        for (int i = 0; i < 8; i++) acc[t][i] = 0.f;

    #pragma unroll
    for (int s = 0; s < 3; s++) {
        cp16(&ws[s][0][0] + tid * 4, g_Be + s * 1024 + tid * 4);
        cp16(&xs[s][tid][0], x + xrow + s * 8);
        cp16(&xs[s][tid][4], x + xrow + s * 8 + 4);
        CP_COMMIT();
    }

    const int mr = w * 32;
    for (int kc = 0; kc < KCH_E; kc++) {
        const int cur = kc & 3;
        CP_WAIT2();
        __syncthreads();

        if (kc + 3 < KCH_E) {
            const int s = (kc + 3) & 3;
            cp16(&ws[s][0][0] + tid * 4, g_Be + (kc + 3) * 1024 + tid * 4);
            cp16(&xs[s][tid][0], x + xrow + (kc + 3) * 8);
            cp16(&xs[s][tid][4], x + xrow + (kc + 3) * 8 + 4);
            CP_COMMIT();
        }

        float2 a0 = *(const float2*)&xs[cur][mr + g     ][2 * tg];
        float2 a1 = *(const float2*)&xs[cur][mr + g +  8][2 * tg];
        float2 a2 = *(const float2*)&xs[cur][mr + g + 16][2 * tg];
        float2 a3 = *(const float2*)&xs[cur][mr + g + 24][2 * tg];
        unsigned ah0[4], al0[4], ah1[4], al1[4];
        splitm(a0.x, ah0[0], al0[0]); splitm(a1.x, ah0[1], al0[1]);
        splitm(a0.y, ah0[2], al0[2]); splitm(a1.y, ah0[3], al0[3]);
        splitm(a2.x, ah1[0], al1[0]); splitm(a3.x, ah1[1], al1[1]);
        splitm(a2.y, ah1[2], al1[2]); splitm(a3.y, ah1[3], al1[3]);

        #pragma unroll
        for (int t = 0; t < 8; t++) {
            float4 bv = *(const float4*)&ws[cur][t * 8 + g][4 * tg];
            mma3(acc[t],     ah0, al0, bv);
            mma3(acc[t] + 4, ah1, al1, bv);
        }
    }

    const int rowb = r0 + mr + g;
    #pragma unroll
    for (int t = 0; t < 8; t++) {
        int col = t * 8 + 2 * tg;
        float2 bb = *(const float2*)(benc + col);
        #pragma unroll
        for (int s = 0; s < 4; s++) {
            int r = rowb + 8 * s;
            if (r < B) {
                float u0 = (s & 1) ? acc[t][(s >> 1) * 4 + 2] : acc[t][(s >> 1) * 4 + 0];
                float u1 = (s & 1) ? acc[t][(s >> 1) * 4 + 3] : acc[t][(s >> 1) * 4 + 1];
                float2 o = make_float2(fmaxf(u0 + bb.x, 0.f), fmaxf(u1 + bb.y, 0.f));
                *(float2*)(hout + (size_t)r * HIDN + col) = o;
            }
        }
    }
}

// ---------------- K2: top-20 gating (32-bit keys) + inline exact repair -----
// Quantized key: (valbits & ~63) | inverted-index. Any boundary ambiguity the
// quantization could introduce (true values differing only in low 6 mantissa
// bits at ranks 20/21) forces thr-nxt == 0 < EPS_GAP -> exact repair path.
__global__ __launch_bounds__(256) void k_topk(const float* __restrict__ x,
        const float* __restrict__ We, const float* __restrict__ benc,
        float* __restrict__ h, int B) {
    int warp = threadIdx.x >> 5, lane = threadIdx.x & 31;
    int row = blockIdx.x * 8 + warp;
    if (row >= B) return;
    float* hr = h + (size_t)row * HIDN;
    float v0 = hr[lane], v1 = hr[lane + 32];

    unsigned q0 = (__float_as_uint(v0) & ~63u) | (unsigned)(63 - lane);
    unsigned q1 = (__float_as_uint(v1) & ~63u) | (unsigned)(31 - lane);
    float thr = 0.f, nxt = 0.f;
    #pragma unroll
    for (int it = 0; it < KTOP + 1; it++) {
        unsigned m = (q0 > q1) ? q0 : q1;
        #pragma unroll
        for (int off = 16; off > 0; off >>= 1) {
            unsigned o = __shfl_xor_sync(0xffffffffu, m, off);
            if (o > m) m = o;
        }
        if (it == KTOP - 1) thr = __uint_as_float(m & ~63u);
        if (it == KTOP)     nxt = __uint_as_float(m & ~63u);
        if (q0 == m) q0 = 0u; else if (q1 == m) q1 = 0u;
    }

    if (thr - nxt >= EPS_GAP) {
        hr[lane]      = (v0 >= thr) ? v0 : 0.f;
        hr[lane + 32] = (v1 >= thr) ? v1 : 0.f;
        return;
    }

    // Fragile: exact fp32 recompute of this row, exact 64-bit-key top-k.
    const float* xr = x + (size_t)row * IN;
    const float* wa = We + (size_t)lane * IN;
    const float* wb = We + (size_t)(lane + 32) * IN;
    float a0 = 0.f, a1 = 0.f;
    for (int k = 0; k < IN; k += 4) {
        float4 xv = *(const float4*)(xr + k);
        float4 va = *(const float4*)(wa + k);
        float4 vb = *(const float4*)(wb + k);
        a0 += xv.x*va.x + xv.y*va.y + xv.z*va.z + xv.w*va.w;
        a1 += xv.x*vb.x + xv.y*vb.y + xv.z*vb.z + xv.w*vb.w;
    }
    v0 = fmaxf(a0 + benc[lane], 0.f);
    v1 = fmaxf(a1 + benc[lane + 32], 0.f);
    unsigned long long k0 = ((unsigned long long)__float_as_uint(v0) << 32) | (unsigned)(63 - lane);
    unsigned long long k1 = ((unsigned long long)__float_as_uint(v1) << 32) | (unsigned)(31 - lane);
    float thx = 0.f;
    #pragma unroll
    for (int it = 0; it < KTOP; it++) {
        unsigned long long m = (k0 > k1) ? k0 : k1;
        #pragma unroll
        for (int off = 16; off > 0; off >>= 1) {
            unsigned long long o = __shfl_xor_sync(0xffffffffu, m, off);
            if (o > m) m = o;
        }
        if (it == KTOP - 1) thx = __uint_as_float((unsigned)(m >> 32));
        if (k0 == m) k0 = 0ull; else if (k1 == m) k1 = 0ull;
    }
    hr[lane]      = (v0 >= thx) ? v0 : 0.f;
    hr[lane + 32] = (v1 >= thx) ? v1 : 0.f;
}

// ---------------- K3: decoder GEMM (3xTF32) + bias ----------------
// CTA = 256 rows x 64 cols (grid.y = 13), warp = 32 rows, K=64 staged once.
__global__ __launch_bounds__(256, 2) void k_dec(const float* __restrict__ h,
        const float* __restrict__ bdec, float* __restrict__ xhat, int B) {
    __shared__ float ws[KCH_D][64][16];   // 32 KB
    const int tid = threadIdx.x, lane = tid & 31, w = tid >> 5;
    const int g = lane >> 2, tg = lane & 3;
    const int r0 = blockIdx.x * 256;
    const int n0 = blockIdx.y * 64;
    const int rowb = r0 + w * 32 + g;
    const float* hp[4];
    #pragma unroll
    for (int j = 0; j < 4; j++) {
        int r = min(rowb + 8 * j, B - 1);
        hp[j] = h + (size_t)r * HIDN + 2 * tg;
    }

    #pragma unroll
    for (int i = 0; i < 8; i++) {
        int f = tid + i * 256;
        int kc = f >> 8, q = f & 255, n = q >> 2, part = q & 3;
        cp16(&ws[kc][n][part * 4],
             g_Bd + ((size_t)kc * NPAD + n0 + n) * 16 + part * 4);
    }
    CP_COMMIT();
    asm volatile("cp.async.wait_group 0;" ::: "memory");
    __syncthreads();

    float acc[8][8];
    #pragma unroll
    for (int t = 0; t < 8; t++)
        #pragma unroll
        for (int i = 0; i < 8; i++) acc[t][i] = 0.f;

    #pragma unroll
    for (int kc = 0; kc < KCH_D; kc++) {
        float2 a0 = *(const float2*)(hp[0] + kc * 8);
        float2 a1 = *(const float2*)(hp[1] + kc * 8);
        float2 a2 = *(const float2*)(hp[2] + kc * 8);
        float2 a3 = *(const float2*)(hp[3] + kc * 8);
        unsigned ah0[4], al0[4], ah1[4], al1[4];
        splitm(a0.x, ah0[0], al0[0]); splitm(a1.x, ah0[1], al0[1]);
        splitm(a0.y, ah0[2], al0[2]); splitm(a1.y, ah0[3], al0[3]);
        splitm(a2.x, ah1[0], al1[0]); splitm(a3.x, ah1[1], al1[1]);
        splitm(a2.y, ah1[2], al1[2]); splitm(a3.y, ah1[3], al1[3]);
        #pragma unroll
        for (int t = 0; t < 8; t++) {
            float4 bv = *(const float4*)&ws[kc][t * 8 + g][4 * tg];
            mma3(acc[t],     ah0, al0, bv);
            mma3(acc[t] + 4, ah1, al1, bv);
        }
    }

    #pragma unroll
    for (int t = 0; t < 8; t++) {
        int col = n0 + t * 8 + 2 * tg;
        if (col < IN) {
            float2 bb = *(const float2*)(bdec + col);
            #pragma unroll
            for (int s = 0; s < 4; s++) {
                int r = rowb + 8 * s;
                if (r < B) {
                    float u0 = (s & 1) ? acc[t][(s >> 1) * 4 + 2] : acc[t][(s >> 1) * 4 + 0];
                    float u1 = (s & 1) ? acc[t][(s >> 1) * 4 + 3] : acc[t][(s >> 1) * 4 + 1];
                    float2 o = make_float2(u0 + bb.x, u1 + bb.y);
                    *(float2*)(xhat + (size_t)r * IN + col) = o;
                }
            }
        }
    }
}

extern "C" void kernel_launch(void* const* d_in, const int* in_sizes, int n_in,
                              void* d_out, int out_size) {
    const float* x    = (const float*)d_in[0];
    const float* We   = (const float*)d_in[1];
    const float* benc = (const float*)d_in[2];
    const float* Wd   = (const float*)d_in[3];
    const float* bdec = (const float*)d_in[4];
    int B = in_sizes[0] / IN;

    float* hout = (float*)d_out;                         // [B, 64]
    float* xhat = (float*)d_out + (size_t)B * HIDN;      // [B, 784]

    const int NPREP = KCH_E * 1024 + KCH_D * NPAD * 16;
    k_prep<<<(NPREP + 255) / 256, 256>>>(We, Wd);
    k_enc<<<(B + 255) / 256, 256>>>(x, benc, hout, B);
    k_topk<<<(B + 7) / 8, 256>>>(x, We, benc, hout, B);
    k_dec<<<dim3((B + 255) / 256, 13), 256>>>(hout, bdec, xhat, B);
}